// round 8
// baseline (speedup 1.0000x reference)
#include <cuda_runtime.h>
#include <cuda_bf16.h>

#define B_     64
#define H_     512
#define W_     512
#define HW_    (H_ * W_)        // 262144
#define TPB    256
#define NBLK   592              // 4 CTAs/SM x 148 SMs, one perfectly-filled wave
#define NTILES 4096             // 8-row tiles: 64 tiles per sample
#define NSLOT  (2 * NBLK)       // each block flushes at most 2 (sample-tagged) slots

// Tagged per-flush partials (AoS). Every slot's tag written each launch.
__device__ float g_fp[NSLOT * 3];   // sp, spt, bce
__device__ int   g_ip[NSLOT * 7];   // st, area, inter, mnx, ylo, mxx, yhi
__device__ int   g_tag[NSLOT];      // sample id or -1
__device__ unsigned int g_cnt;      // block completion counter (zero-init, reset by last block)

__device__ __forceinline__ float tanh_approx(float x) {
    float r;
    asm("tanh.approx.f32 %0, %1;" : "=f"(r) : "f"(x));
    return r;
}

__device__ __forceinline__ float warp_sum_f(float v) {
    #pragma unroll
    for (int o = 16; o > 0; o >>= 1) v += __shfl_down_sync(0xffffffffu, v, o);
    return v;
}
__device__ __forceinline__ int warp_sum_i(int v) {
    #pragma unroll
    for (int o = 16; o > 0; o >>= 1) v += __shfl_down_sync(0xffffffffu, v, o);
    return v;
}
__device__ __forceinline__ int warp_min_i(int v) {
    #pragma unroll
    for (int o = 16; o > 0; o >>= 1) v = min(v, __shfl_down_sync(0xffffffffu, v, o));
    return v;
}
__device__ __forceinline__ int warp_max_i(int v) {
    #pragma unroll
    for (int o = 16; o > 0; o >>= 1) v = max(v, __shfl_down_sync(0xffffffffu, v, o));
    return v;
}

// ---------- scalar box helpers ----------
__device__ __forceinline__ void xywh2xyxy(const float* w, float* x) {
    x[0] = w[0] - w[2] * 0.5f; x[1] = w[1] - w[3] * 0.5f;
    x[2] = w[0] + w[2] * 0.5f; x[3] = w[1] + w[3] * 0.5f;
}
__device__ __forceinline__ void xyxy2xywh(const float* x, float* w) {
    w[0] = (x[0] + x[2]) * 0.5f; w[1] = (x[1] + x[3]) * 0.5f;
    w[2] = x[2] - x[0];          w[3] = x[3] - x[1];
}
__device__ __forceinline__ float giou_xyxy(const float* a, const float* b) {
    const float ix1 = fmaxf(a[0], b[0]), iy1 = fmaxf(a[1], b[1]);
    const float ix2 = fminf(a[2], b[2]), iy2 = fminf(a[3], b[3]);
    const float inter = fmaxf(ix2 - ix1, 0.f) * fmaxf(iy2 - iy1, 0.f);
    const float aa = fmaxf(a[2] - a[0], 0.f) * fmaxf(a[3] - a[1], 0.f);
    const float ab = fmaxf(b[2] - b[0], 0.f) * fmaxf(b[3] - b[1], 0.f);
    const float un = aa + ab - inter;
    const float iou = inter / fmaxf(un, 1e-6f);
    const float cx1 = fminf(a[0], b[0]), cy1 = fminf(a[1], b[1]);
    const float cx2 = fmaxf(a[2], b[2]), cy2 = fmaxf(a[3], b[3]);
    const float cc = fmaxf(cx2 - cx1, 0.f) * fmaxf(cy2 - cy1, 0.f);
    return iou - (cc - un) / fmaxf(cc, 1e-6f);
}
__device__ __forceinline__ float box_loss(const float* pw, const float* tw) {
    const float l1 = fabsf(pw[0] - tw[0]) + fabsf(pw[1] - tw[1]) +
                     fabsf(pw[2] - tw[2]) + fabsf(pw[3] - tw[3]);
    float ax[4], bx[4];
    xywh2xyxy(pw, ax); xywh2xyxy(tw, bx);
    return l1 + (1.0f - giou_xyxy(ax, bx));
}

__global__ __launch_bounds__(TPB, 4) void uh_fused_kernel(
    const float* __restrict__ logits,   // (B,1,H,W)
    const int*   __restrict__ tgt,      // (B,H,W)
    const float* __restrict__ pbox,     // (B,4) xywh normalized
    const float* __restrict__ gbox,     // (B,4)
    float* __restrict__ out)
{
    const int bid  = blockIdx.x;
    const int tid  = threadIdx.x;
    const int xq   = tid & 127;          // float4 column index [0,128)
    const int half = tid >> 7;           // 0/1
    const int x0   = xq << 2;            // pixel column base
    const int lane = tid & 31, wid = tid >> 5;

    __shared__ float shf[3][TPB / 32];
    __shared__ int   shi[7][TPB / 32];

    // Balanced contiguous tile run: 6 or 7 tiles per block
    const int t0 = (int)(((long long)bid * NTILES) / NBLK);
    const int t1 = (int)(((long long)(bid + 1) * NTILES) / NBLK);

    int cur_s = t0 >> 6;
    int x1p, x2p, y1p, y2p, xin;

    auto load_box = [&](int s) {
        const float cx = pbox[s * 4 + 0], cy = pbox[s * 4 + 1];
        const float bw = pbox[s * 4 + 2], bh = pbox[s * 4 + 3];
        x1p = min(max((int)((cx - bw * 0.5f) * (float)W_), 0), W_);
        x2p = min(max((int)((cx + bw * 0.5f) * (float)W_), 0), W_);
        y1p = min(max((int)((cy - bh * 0.5f) * (float)H_), 0), H_);
        y2p = min(max((int)((cy + bh * 0.5f) * (float)H_), 0), H_);
        xin = 0;
        #pragma unroll
        for (int j = 0; j < 4; ++j)
            if (x0 + j >= x1p && x0 + j < x2p) xin |= 1 << j;
    };
    load_box(cur_s);

    float sps = 0.f, sptq = 0.f, sbx = 0.f, slg = 0.f;
    int st = 0, tneg = 0, area = 0, inter = 0, apos = 0;
    int ylo = H_, yhi = -1, ntile = 0;
    int flush_idx = 0;

    // Block-reduce current accumulators and store tagged slot (uniform call)
    auto flush = [&]() {
        const float sp   = 16.0f * (float)ntile - (float)area + sps;  // 16 px/thread/tile
        const float spt  = (float)tneg + sptq;
        const float sbce = sbx - 0.69314718055994531f * slg;
        const int mnx = apos ? (x0 + (__ffs(apos) - 1)) : W_;
        const int mxx = apos ? (x0 + (31 - __clz(apos))) : -1;

        float rsp  = warp_sum_f(sp);
        float rspt = warp_sum_f(spt);
        float rbce = warp_sum_f(sbce);
        int rst    = warp_sum_i(st);
        int rarea  = warp_sum_i(area);
        int rinter = warp_sum_i(inter);
        int rmnx   = warp_min_i(mnx);
        int rylo   = warp_min_i(ylo);
        int rmxx   = warp_max_i(mxx);
        int ryhi   = warp_max_i(yhi);

        __syncthreads();   // protect smem from previous flush
        if (lane == 0) {
            shf[0][wid] = rsp;  shf[1][wid] = rspt; shf[2][wid] = rbce;
            shi[0][wid] = rst;  shi[1][wid] = rarea; shi[2][wid] = rinter;
            shi[3][wid] = rmnx; shi[4][wid] = rylo;  shi[5][wid] = rmxx; shi[6][wid] = ryhi;
        }
        __syncthreads();
        if (tid == 0) {
            float a0 = shf[0][0], a1 = shf[1][0], a2 = shf[2][0];
            int i0 = shi[0][0], i1 = shi[1][0], i2 = shi[2][0];
            int i3 = shi[3][0], i4 = shi[4][0], i5 = shi[5][0], i6 = shi[6][0];
            #pragma unroll
            for (int w = 1; w < TPB / 32; ++w) {
                a0 += shf[0][w]; a1 += shf[1][w]; a2 += shf[2][w];
                i0 += shi[0][w]; i1 += shi[1][w]; i2 += shi[2][w];
                i3 = min(i3, shi[3][w]); i4 = min(i4, shi[4][w]);
                i5 = max(i5, shi[5][w]); i6 = max(i6, shi[6][w]);
            }
            const int slot = 2 * bid + flush_idx;
            g_fp[slot * 3 + 0] = a0;
            g_fp[slot * 3 + 1] = a1;
            g_fp[slot * 3 + 2] = a2;
            g_ip[slot * 7 + 0] = i0;
            g_ip[slot * 7 + 1] = i1;
            g_ip[slot * 7 + 2] = i2;
            g_ip[slot * 7 + 3] = i3;
            g_ip[slot * 7 + 4] = i4;
            g_ip[slot * 7 + 5] = i5;
            g_ip[slot * 7 + 6] = i6;
            g_tag[slot] = cur_s;
        }
        flush_idx++;
    };

    for (int t = t0; t < t1; ++t) {
        const int lt = t & 63;
        const int rowbase = lt * 8;
        const float4* lp = (const float4*)(logits + (size_t)cur_s * HW_) +
                           (((size_t)(rowbase + half)) << 7) + xq;
        const int4*   tp = (const int4*)(tgt + (size_t)cur_s * HW_) +
                           (((size_t)(rowbase + half)) << 7) + xq;

        float4 xv[4];
        int4   tv[4];
        #pragma unroll
        for (int u = 0; u < 4; ++u) {     // 8 LDG.128 batched -> MLP ~8
            xv[u] = lp[(size_t)u * 256];
            tv[u] = tp[(size_t)u * 256];
        }

        #pragma unroll
        for (int u = 0; u < 4; ++u) {
            const int y = rowbase + 2 * u + half;
            const bool yin = (y >= y1p) && (y < y2p);
            const float xs[4] = {xv[u].x, xv[u].y, xv[u].z, xv[u].w};
            const int   ti[4] = {tv[u].x, tv[u].y, tv[u].z, tv[u].w};

            int pb = 0;
            #pragma unroll
            for (int j = 0; j < 4; ++j) {
                const float x = xs[j];
                const float th = tanh_approx(0.5f * fabsf(x));   // 1 MUFU
                const float p0 = fmaf(0.5f, th, 0.5f);           // sigmoid(|x|)
                slg += __log2f(p0);                              // log1p(e^-|x|) = -ln2*log2(p0)
                const bool pos = (x > 0.0f);
                const bool tnz = (ti[j] != 0);
                const float q = pos ? p0 : -p0;
                sps  += q;
                sptq += tnz ? q : 0.0f;
                sbx  += fmaxf(tnz ? -x : x, 0.0f);               // max(x,0) - x*t
                pb   |= pos ? (1 << j) : 0;
            }
            const int tb = ti[0] + 2 * ti[1] + 4 * ti[2] + 8 * ti[3];
            st   += __popc(tb);
            tneg += __popc(tb & ~pb);
            area += __popc(pb);
            apos |= pb;
            ylo = min(ylo, pb ? y : H_);
            yhi = max(yhi, pb ? y : -1);
            inter += yin ? __popc(pb & xin) : 0;
        }
        ntile++;

        const bool boundary = (t + 1 == t1) || (((t + 1) >> 6) != cur_s);
        if (boundary) {                    // uniform across block
            flush();
            if (t + 1 < t1) {
                cur_s = (t + 1) >> 6;
                load_box(cur_s);
                sps = sptq = sbx = slg = 0.f;
                st = tneg = area = inter = apos = 0;
                ylo = H_; yhi = -1; ntile = 0;
            }
        }
    }

    __shared__ bool s_is_last;
    if (tid == 0) {
        if (flush_idx < 2) g_tag[2 * bid + 1] = -1;   // mark unused slot
        __threadfence();
        const unsigned int prev = atomicAdd(&g_cnt, 1u);
        s_is_last = (prev == (unsigned int)(NBLK - 1));
    }
    __syncthreads();
    if (!s_is_last) return;
    __threadfence();   // acquire: see all partials

    // ================= FINALIZE (last block only) =================
    __shared__ float s_dice[B_], s_bce[B_], s_s2b[B_], s_b2s[B_], s_det[B_];

    if (tid < B_) {
        const int s = tid;
        // blocks whose runs can touch sample s
        const int i_first = (int)(((long long)(64 * s) * NBLK) >> 12);
        const int i_last  = (int)(((long long)(64 * s + 63) * NBLK) >> 12);

        float fsp = 0.f, fspt = 0.f, fsbce = 0.f;
        int fst = 0, farea = 0, finter = 0;
        int fmnx = W_, fmny = H_, fmxx = -1, fmxy = -1;
        for (int i = i_first; i <= i_last; ++i) {
            #pragma unroll
            for (int k = 0; k < 2; ++k) {
                const int slot = 2 * i + k;
                if (g_tag[slot] != s) continue;
                fsp   += g_fp[slot * 3 + 0];
                fspt  += g_fp[slot * 3 + 1];
                fsbce += g_fp[slot * 3 + 2];
                fst   += g_ip[slot * 7 + 0];
                farea += g_ip[slot * 7 + 1];
                finter+= g_ip[slot * 7 + 2];
                fmnx = min(fmnx, g_ip[slot * 7 + 3]);
                fmny = min(fmny, g_ip[slot * 7 + 4]);
                fmxx = max(fmxx, g_ip[slot * 7 + 5]);
                fmxy = max(fmxy, g_ip[slot * 7 + 6]);
            }
        }

        // dice
        const float dice = 1.0f - (2.0f * fspt + 1.0f) / (fsp + (float)fst + 1.0f);

        // s2b
        const float iou_s2b = (farea > 0) ? ((float)finter / fmaxf((float)farea, 1.0f)) : 0.0f;
        const float s2b = 1.0f - iou_s2b;

        // b2s
        float pbv[4] = {pbox[s*4+0], pbox[s*4+1], pbox[s*4+2], pbox[s*4+3]};
        float box_xyxy[4];
        xywh2xyxy(pbv, box_xyxy);
        float outer[4];
        if (farea > 0) {
            outer[0] = (float)fmnx; outer[1] = (float)fmny;
            outer[2] = (float)fmxx; outer[3] = (float)fmxy;
        } else {
            outer[0] = outer[1] = outer[2] = outer[3] = 0.0f;
        }
        outer[0] /= (float)W_; outer[1] /= (float)H_;
        outer[2] /= (float)W_; outer[3] /= (float)H_;
        float pred_w[4], tgt_w[4];
        xyxy2xywh(outer, pred_w);
        xyxy2xywh(box_xyxy, tgt_w);
        const float b2s = box_loss(pred_w, tgt_w);

        // det
        float g[4] = {gbox[s*4+0], gbox[s*4+1], gbox[s*4+2], gbox[s*4+3]};
        const float gx1 = g[0] * (0.45f * (float)W_);
        const float gy1 = g[1] * (0.45f * (float)H_);
        const float gx2 = gx1 + 1.0f + g[2] * (0.5f * (float)W_);
        const float gy2 = gy1 + 1.0f + g[3] * (0.5f * (float)H_);
        float gxyxy[4] = {gx1, gy1, gx2, gy2};
        float gtw[4];
        xyxy2xywh(gxyxy, gtw);
        gtw[0] /= (float)H_; gtw[1] /= (float)W_;
        gtw[2] /= (float)H_; gtw[3] /= (float)W_;
        const float det = box_loss(pbv, gtw);

        s_dice[s] = dice; s_bce[s] = fsbce; s_s2b[s] = s2b; s_b2s[s] = b2s; s_det[s] = det;
    }
    __syncthreads();

    if (tid == 0) {
        float td = 0.f, tb = 0.f, ts2 = 0.f, t2 = 0.f, te = 0.f;
        for (int i = 0; i < B_; ++i) {
            td += s_dice[i]; tb += s_bce[i]; ts2 += s_s2b[i];
            t2 += s_b2s[i];  te += s_det[i];
        }
        const float inv_b = 1.0f / (float)B_;
        out[0] = td * inv_b
               + tb / ((float)B_ * (float)HW_)
               + te * inv_b * 0.025f
               + ts2 * inv_b
               + t2 * inv_b;
        g_cnt = 0;   // reset for next graph replay (deterministic)
    }
}

extern "C" void kernel_launch(void* const* d_in, const int* in_sizes, int n_in,
                              void* d_out, int out_size) {
    const float* pred_mask = (const float*)d_in[0];   // (64,1,512,512)
    const float* pred_bbox = (const float*)d_in[1];   // (64,4)
    const float* gt_bbox   = (const float*)d_in[2];   // (64,4)
    const int*   tgt_mask  = (const int*)  d_in[3];   // (64,512,512)
    float* out = (float*)d_out;

    uh_fused_kernel<<<NBLK, TPB>>>(pred_mask, tgt_mask, pred_bbox, gt_bbox, out);
}

// round 9
// speedup vs baseline: 1.1846x; 1.1846x over previous
#include <cuda_runtime.h>
#include <cuda_bf16.h>

#define B_   64
#define H_   512
#define W_   512
#define HW_  (H_ * W_)          // 262144
#define BPS  8                  // tiles per sample (64 rows each) -> 512 blocks total
#define TPB  256
#define NSLOT (B_ * BPS)        // 512 partial slots (== total blocks)

// Per-block partial reductions (SoA). Every slot written each launch -> no init needed.
__device__ float g_fp[3 * NSLOT];   // [0]=sum_p [1]=sum_pt [2]=sum_bce
__device__ int   g_ip[7 * NSLOT];   // [0]=sum_t [1]=area [2]=inter [3]=minx [4]=miny [5]=maxx [6]=maxy
__device__ unsigned int g_cnt;      // block completion counter (zero-init, reset by last block)

__device__ __forceinline__ float tanh_approx(float x) {
    float r;
    asm("tanh.approx.f32 %0, %1;" : "=f"(r) : "f"(x));
    return r;
}

__device__ __forceinline__ float warp_sum_f(float v) {
    #pragma unroll
    for (int o = 16; o > 0; o >>= 1) v += __shfl_down_sync(0xffffffffu, v, o);
    return v;
}
__device__ __forceinline__ int warp_sum_i(int v) {
    #pragma unroll
    for (int o = 16; o > 0; o >>= 1) v += __shfl_down_sync(0xffffffffu, v, o);
    return v;
}
__device__ __forceinline__ int warp_min_i(int v) {
    #pragma unroll
    for (int o = 16; o > 0; o >>= 1) v = min(v, __shfl_down_sync(0xffffffffu, v, o));
    return v;
}
__device__ __forceinline__ int warp_max_i(int v) {
    #pragma unroll
    for (int o = 16; o > 0; o >>= 1) v = max(v, __shfl_down_sync(0xffffffffu, v, o));
    return v;
}

// ---------- scalar box helpers ----------
__device__ __forceinline__ void xywh2xyxy(const float* w, float* x) {
    x[0] = w[0] - w[2] * 0.5f; x[1] = w[1] - w[3] * 0.5f;
    x[2] = w[0] + w[2] * 0.5f; x[3] = w[1] + w[3] * 0.5f;
}
__device__ __forceinline__ void xyxy2xywh(const float* x, float* w) {
    w[0] = (x[0] + x[2]) * 0.5f; w[1] = (x[1] + x[3]) * 0.5f;
    w[2] = x[2] - x[0];          w[3] = x[3] - x[1];
}
__device__ __forceinline__ float giou_xyxy(const float* a, const float* b) {
    const float ix1 = fmaxf(a[0], b[0]), iy1 = fmaxf(a[1], b[1]);
    const float ix2 = fminf(a[2], b[2]), iy2 = fminf(a[3], b[3]);
    const float inter = fmaxf(ix2 - ix1, 0.f) * fmaxf(iy2 - iy1, 0.f);
    const float aa = fmaxf(a[2] - a[0], 0.f) * fmaxf(a[3] - a[1], 0.f);
    const float ab = fmaxf(b[2] - b[0], 0.f) * fmaxf(b[3] - b[1], 0.f);
    const float un = aa + ab - inter;
    const float iou = inter / fmaxf(un, 1e-6f);
    const float cx1 = fminf(a[0], b[0]), cy1 = fminf(a[1], b[1]);
    const float cx2 = fmaxf(a[2], b[2]), cy2 = fmaxf(a[3], b[3]);
    const float cc = fmaxf(cx2 - cx1, 0.f) * fmaxf(cy2 - cy1, 0.f);
    return iou - (cc - un) / fmaxf(cc, 1e-6f);
}
__device__ __forceinline__ float box_loss(const float* pw, const float* tw) {
    const float l1 = fabsf(pw[0] - tw[0]) + fabsf(pw[1] - tw[1]) +
                     fabsf(pw[2] - tw[2]) + fabsf(pw[3] - tw[3]);
    float ax[4], bx[4];
    xywh2xyxy(pw, ax); xywh2xyxy(tw, bx);
    return l1 + (1.0f - giou_xyxy(ax, bx));
}

__global__ __launch_bounds__(TPB, 4) void uh_fused_kernel(
    const float* __restrict__ logits,   // (B,1,H,W)
    const int*   __restrict__ tgt,      // (B,H,W)
    const float* __restrict__ pbox,     // (B,4) xywh normalized
    const float* __restrict__ gbox,     // (B,4)
    float* __restrict__ out)
{
    const int b   = blockIdx.y;
    const int c   = blockIdx.x;
    const int tid = threadIdx.x;

    const int xq   = tid & 127;          // float4 column index [0,128)
    const int half = tid >> 7;           // 0/1
    const int x0   = xq << 2;            // pixel column base

    // Box in pixel coords
    const float cx = pbox[b * 4 + 0], cy = pbox[b * 4 + 1];
    const float bw = pbox[b * 4 + 2], bh = pbox[b * 4 + 3];
    const int x1p = min(max((int)((cx - bw * 0.5f) * (float)W_), 0), W_);
    const int x2p = min(max((int)((cx + bw * 0.5f) * (float)W_), 0), W_);
    const int y1p = min(max((int)((cy - bh * 0.5f) * (float)H_), 0), H_);
    const int y2p = min(max((int)((cy + bh * 0.5f) * (float)H_), 0), H_);

    int xin = 0;
    #pragma unroll
    for (int j = 0; j < 4; ++j)
        if (x0 + j >= x1p && x0 + j < x2p) xin |= 1 << j;

    const int rowbase = c * 64;
    const float4* lg4 = (const float4*)(logits + (size_t)b * HW_) +
                        (((size_t)(rowbase + half)) << 7) + xq;
    const int4*   tg4 = (const int4*)  (tgt    + (size_t)b * HW_) +
                        (((size_t)(rowbase + half)) << 7) + xq;

    float sps = 0.f, sptq = 0.f, sbx = 0.f, slg = 0.f;
    int st = 0, tneg = 0, area = 0, inter = 0, apos = 0;
    unsigned int rowm = 0;   // bit k set <=> any positive in row-pair k

    // ---- software-pipelined main loop: 16 steps of 2 row-pairs ----
    float4 xA[2], xB[2];
    int4   tA[2], tB[2];

    #define LOADP(BUF_X, BUF_T, S)                                 \
        do {                                                       \
            BUF_X[0] = lg4[(size_t)(2 * (S) + 0) * 256];           \
            BUF_X[1] = lg4[(size_t)(2 * (S) + 1) * 256];           \
            BUF_T[0] = tg4[(size_t)(2 * (S) + 0) * 256];           \
            BUF_T[1] = tg4[(size_t)(2 * (S) + 1) * 256];           \
        } while (0)

    #define PROCP(BUF_X, BUF_T, S)                                             \
        do {                                                                   \
            _Pragma("unroll")                                                  \
            for (int u = 0; u < 2; ++u) {                                      \
                const int k = 2 * (S) + u;                                     \
                const int y = rowbase + 2 * k + half;                          \
                const bool yin = (y >= y1p) && (y < y2p);                      \
                const float xs[4] = {BUF_X[u].x, BUF_X[u].y,                   \
                                     BUF_X[u].z, BUF_X[u].w};                  \
                const int   ti[4] = {BUF_T[u].x, BUF_T[u].y,                   \
                                     BUF_T[u].z, BUF_T[u].w};                  \
                int pb = 0;                                                    \
                _Pragma("unroll")                                              \
                for (int j = 0; j < 4; ++j) {                                  \
                    const float x = xs[j];                                     \
                    const float th = tanh_approx(0.5f * fabsf(x));             \
                    const float p0 = fmaf(0.5f, th, 0.5f);                     \
                    slg += __log2f(p0);                                        \
                    const bool pos = (x > 0.0f);                               \
                    const bool tnz = (ti[j] != 0);                             \
                    const float q = pos ? p0 : -p0;                            \
                    sps  += q;                                                 \
                    sptq += tnz ? q : 0.0f;                                    \
                    sbx  += fmaxf(tnz ? -x : x, 0.0f);                         \
                    pb   |= pos ? (1 << j) : 0;                                \
                }                                                              \
                const int tb = ti[0] + 2 * ti[1] + 4 * ti[2] + 8 * ti[3];      \
                st   += __popc(tb);                                            \
                tneg += __popc(tb & ~pb);                                      \
                area += __popc(pb);                                            \
                apos |= pb;                                                    \
                rowm |= pb ? (1u << k) : 0u;                                   \
                inter += yin ? __popc(pb & xin) : 0;                           \
            }                                                                  \
        } while (0)

    LOADP(xA, tA, 0);                     // prologue
    #pragma unroll 2
    for (int m = 0; m < 7; ++m) {
        LOADP(xB, tB, 2 * m + 1);         // prefetch next while A in regs
        PROCP(xA, tA, 2 * m);
        LOADP(xA, tA, 2 * m + 2);         // prefetch next-next
        PROCP(xB, tB, 2 * m + 1);
    }
    LOADP(xB, tB, 15);                    // epilogue
    PROCP(xA, tA, 14);
    PROCP(xB, tB, 15);

    #undef LOADP
    #undef PROCP

    const float sp   = 128.0f - (float)area + sps;           // 128 px per thread
    const float spt  = (float)tneg + sptq;
    const float sbce = sbx - 0.69314718055994531f * slg;

    const int mnx = apos ? (x0 + (__ffs(apos) - 1)) : W_;
    const int mxx = apos ? (x0 + (31 - __clz(apos))) : -1;
    const int ylo = rowm ? (rowbase + 2 * (__ffs((int)rowm) - 1) + half) : H_;
    const int yhi = rowm ? (rowbase + 2 * (31 - __clz((int)rowm)) + half) : -1;

    // Block reduce (warp shuffle + shared)
    __shared__ float shf[3][TPB / 32];
    __shared__ int   shi[7][TPB / 32];
    const int lane = tid & 31, wid = tid >> 5;

    float rsp  = warp_sum_f(sp);
    float rspt = warp_sum_f(spt);
    float rbce = warp_sum_f(sbce);
    int rst    = warp_sum_i(st);
    int rarea  = warp_sum_i(area);
    int rinter = warp_sum_i(inter);
    int rmnx   = warp_min_i(mnx);
    int rylo   = warp_min_i(ylo);
    int rmxx   = warp_max_i(mxx);
    int ryhi   = warp_max_i(yhi);

    if (lane == 0) {
        shf[0][wid] = rsp;  shf[1][wid] = rspt; shf[2][wid] = rbce;
        shi[0][wid] = rst;  shi[1][wid] = rarea; shi[2][wid] = rinter;
        shi[3][wid] = rmnx; shi[4][wid] = rylo;  shi[5][wid] = rmxx; shi[6][wid] = ryhi;
    }
    __syncthreads();

    __shared__ bool s_is_last;
    if (tid == 0) {
        float a0 = shf[0][0], a1 = shf[1][0], a2 = shf[2][0];
        int i0 = shi[0][0], i1 = shi[1][0], i2 = shi[2][0];
        int i3 = shi[3][0], i4 = shi[4][0], i5 = shi[5][0], i6 = shi[6][0];
        #pragma unroll
        for (int w = 1; w < TPB / 32; ++w) {
            a0 += shf[0][w]; a1 += shf[1][w]; a2 += shf[2][w];
            i0 += shi[0][w]; i1 += shi[1][w]; i2 += shi[2][w];
            i3 = min(i3, shi[3][w]); i4 = min(i4, shi[4][w]);
            i5 = max(i5, shi[5][w]); i6 = max(i6, shi[6][w]);
        }
        const int slot = b * BPS + c;
        g_fp[0 * NSLOT + slot] = a0;
        g_fp[1 * NSLOT + slot] = a1;
        g_fp[2 * NSLOT + slot] = a2;
        g_ip[0 * NSLOT + slot] = i0;
        g_ip[1 * NSLOT + slot] = i1;
        g_ip[2 * NSLOT + slot] = i2;
        g_ip[3 * NSLOT + slot] = i3;
        g_ip[4 * NSLOT + slot] = i4;
        g_ip[5 * NSLOT + slot] = i5;
        g_ip[6 * NSLOT + slot] = i6;

        __threadfence();
        const unsigned int prev = atomicAdd(&g_cnt, 1u);
        s_is_last = (prev == (unsigned int)(NSLOT - 1));
    }
    __syncthreads();
    if (!s_is_last) return;
    __threadfence();   // acquire: see all partials

    // ================= FINALIZE (last block only) =================
    __shared__ float s_dice[B_], s_bce[B_], s_s2b[B_], s_b2s[B_], s_det[B_];

    if (tid < B_) {
        const int s = tid;
        float fsp = 0.f, fspt = 0.f, fsbce = 0.f;
        int fst = 0, farea = 0, finter = 0;
        int fmnx = W_, fmny = H_, fmxx = -1, fmxy = -1;
        #pragma unroll
        for (int cc = 0; cc < BPS; ++cc) {
            const int slot = s * BPS + cc;
            fsp   += g_fp[0 * NSLOT + slot];
            fspt  += g_fp[1 * NSLOT + slot];
            fsbce += g_fp[2 * NSLOT + slot];
            fst   += g_ip[0 * NSLOT + slot];
            farea += g_ip[1 * NSLOT + slot];
            finter+= g_ip[2 * NSLOT + slot];
            fmnx = min(fmnx, g_ip[3 * NSLOT + slot]);
            fmny = min(fmny, g_ip[4 * NSLOT + slot]);
            fmxx = max(fmxx, g_ip[5 * NSLOT + slot]);
            fmxy = max(fmxy, g_ip[6 * NSLOT + slot]);
        }

        const float dice = 1.0f - (2.0f * fspt + 1.0f) / (fsp + (float)fst + 1.0f);

        const float iou_s2b = (farea > 0) ? ((float)finter / fmaxf((float)farea, 1.0f)) : 0.0f;
        const float s2b = 1.0f - iou_s2b;

        float pbv[4] = {pbox[s*4+0], pbox[s*4+1], pbox[s*4+2], pbox[s*4+3]};
        float box_xyxy[4];
        xywh2xyxy(pbv, box_xyxy);
        float outer[4];
        if (farea > 0) {
            outer[0] = (float)fmnx; outer[1] = (float)fmny;
            outer[2] = (float)fmxx; outer[3] = (float)fmxy;
        } else {
            outer[0] = outer[1] = outer[2] = outer[3] = 0.0f;
        }
        outer[0] /= (float)W_; outer[1] /= (float)H_;
        outer[2] /= (float)W_; outer[3] /= (float)H_;
        float pred_w[4], tgt_w[4];
        xyxy2xywh(outer, pred_w);
        xyxy2xywh(box_xyxy, tgt_w);
        const float b2s = box_loss(pred_w, tgt_w);

        float g[4] = {gbox[s*4+0], gbox[s*4+1], gbox[s*4+2], gbox[s*4+3]};
        const float gx1 = g[0] * (0.45f * (float)W_);
        const float gy1 = g[1] * (0.45f * (float)H_);
        const float gx2 = gx1 + 1.0f + g[2] * (0.5f * (float)W_);
        const float gy2 = gy1 + 1.0f + g[3] * (0.5f * (float)H_);
        float gxyxy[4] = {gx1, gy1, gx2, gy2};
        float gtw[4];
        xyxy2xywh(gxyxy, gtw);
        gtw[0] /= (float)H_; gtw[1] /= (float)W_;
        gtw[2] /= (float)H_; gtw[3] /= (float)W_;
        const float det = box_loss(pbv, gtw);

        s_dice[s] = dice; s_bce[s] = fsbce; s_s2b[s] = s2b; s_b2s[s] = b2s; s_det[s] = det;
    }
    __syncthreads();

    if (tid == 0) {
        float td = 0.f, tb = 0.f, ts2 = 0.f, t2 = 0.f, te = 0.f;
        for (int i = 0; i < B_; ++i) {
            td += s_dice[i]; tb += s_bce[i]; ts2 += s_s2b[i];
            t2 += s_b2s[i];  te += s_det[i];
        }
        const float inv_b = 1.0f / (float)B_;
        out[0] = td * inv_b
               + tb / ((float)B_ * (float)HW_)
               + te * inv_b * 0.025f
               + ts2 * inv_b
               + t2 * inv_b;
        g_cnt = 0;   // reset for next graph replay
    }
}

extern "C" void kernel_launch(void* const* d_in, const int* in_sizes, int n_in,
                              void* d_out, int out_size) {
    const float* pred_mask = (const float*)d_in[0];   // (64,1,512,512)
    const float* pred_bbox = (const float*)d_in[1];   // (64,4)
    const float* gt_bbox   = (const float*)d_in[2];   // (64,4)
    const int*   tgt_mask  = (const int*)  d_in[3];   // (64,512,512)
    float* out = (float*)d_out;

    dim3 grid(BPS, B_);
    uh_fused_kernel<<<grid, TPB>>>(pred_mask, tgt_mask, pred_bbox, gt_bbox, out);
}

// round 10
// speedup vs baseline: 1.2623x; 1.0656x over previous
#include <cuda_runtime.h>
#include <cuda_bf16.h>

#define B_   64
#define H_   512
#define W_   512
#define HW_  (H_ * W_)          // 262144
#define BPS  8                  // tiles per sample (64 rows each) -> 512 blocks total
#define TPB  256
#define NSLOT (B_ * BPS)        // 512 partial slots (== total blocks)

// Per-block partial reductions (SoA). Every slot written each launch -> no init needed.
__device__ float g_fp[3 * NSLOT];   // [0]=sum_p [1]=sum_pt [2]=sum_bce
__device__ int   g_ip[7 * NSLOT];   // [0]=sum_t [1]=area [2]=inter [3]=minx [4]=miny [5]=maxx [6]=maxy
__device__ unsigned int g_cnt;      // block completion counter (zero-init, reset by last block)

__device__ __forceinline__ float tanh_approx(float x) {
    float r;
    asm("tanh.approx.f32 %0, %1;" : "=f"(r) : "f"(x));
    return r;
}

__device__ __forceinline__ float warp_sum_f(float v) {
    #pragma unroll
    for (int o = 16; o > 0; o >>= 1) v += __shfl_down_sync(0xffffffffu, v, o);
    return v;
}
__device__ __forceinline__ int warp_sum_i(int v) {
    #pragma unroll
    for (int o = 16; o > 0; o >>= 1) v += __shfl_down_sync(0xffffffffu, v, o);
    return v;
}
__device__ __forceinline__ int warp_min_i(int v) {
    #pragma unroll
    for (int o = 16; o > 0; o >>= 1) v = min(v, __shfl_down_sync(0xffffffffu, v, o));
    return v;
}
__device__ __forceinline__ int warp_max_i(int v) {
    #pragma unroll
    for (int o = 16; o > 0; o >>= 1) v = max(v, __shfl_down_sync(0xffffffffu, v, o));
    return v;
}

// ---------- scalar box helpers ----------
__device__ __forceinline__ void xywh2xyxy(const float* w, float* x) {
    x[0] = w[0] - w[2] * 0.5f; x[1] = w[1] - w[3] * 0.5f;
    x[2] = w[0] + w[2] * 0.5f; x[3] = w[1] + w[3] * 0.5f;
}
__device__ __forceinline__ void xyxy2xywh(const float* x, float* w) {
    w[0] = (x[0] + x[2]) * 0.5f; w[1] = (x[1] + x[3]) * 0.5f;
    w[2] = x[2] - x[0];          w[3] = x[3] - x[1];
}
__device__ __forceinline__ float giou_xyxy(const float* a, const float* b) {
    const float ix1 = fmaxf(a[0], b[0]), iy1 = fmaxf(a[1], b[1]);
    const float ix2 = fminf(a[2], b[2]), iy2 = fminf(a[3], b[3]);
    const float inter = fmaxf(ix2 - ix1, 0.f) * fmaxf(iy2 - iy1, 0.f);
    const float aa = fmaxf(a[2] - a[0], 0.f) * fmaxf(a[3] - a[1], 0.f);
    const float ab = fmaxf(b[2] - b[0], 0.f) * fmaxf(b[3] - b[1], 0.f);
    const float un = aa + ab - inter;
    const float iou = inter / fmaxf(un, 1e-6f);
    const float cx1 = fminf(a[0], b[0]), cy1 = fminf(a[1], b[1]);
    const float cx2 = fmaxf(a[2], b[2]), cy2 = fmaxf(a[3], b[3]);
    const float cc = fmaxf(cx2 - cx1, 0.f) * fmaxf(cy2 - cy1, 0.f);
    return iou - (cc - un) / fmaxf(cc, 1e-6f);
}
__device__ __forceinline__ float box_loss(const float* pw, const float* tw) {
    const float l1 = fabsf(pw[0] - tw[0]) + fabsf(pw[1] - tw[1]) +
                     fabsf(pw[2] - tw[2]) + fabsf(pw[3] - tw[3]);
    float ax[4], bx[4];
    xywh2xyxy(pw, ax); xywh2xyxy(tw, bx);
    return l1 + (1.0f - giou_xyxy(ax, bx));
}

__global__ __launch_bounds__(TPB, 4) void uh_fused_kernel(
    const float* __restrict__ logits,   // (B,1,H,W)
    const int*   __restrict__ tgt,      // (B,H,W)
    const float* __restrict__ pbox,     // (B,4) xywh normalized
    const float* __restrict__ gbox,     // (B,4)
    float* __restrict__ out)
{
    const int b   = blockIdx.y;
    const int c   = blockIdx.x;
    const int tid = threadIdx.x;

    const int xq   = tid & 127;          // float4 column index [0,128)
    const int half = tid >> 7;           // 0/1
    const int x0   = xq << 2;            // pixel column base

    // Box in pixel coords
    const float cx = pbox[b * 4 + 0], cy = pbox[b * 4 + 1];
    const float bw = pbox[b * 4 + 2], bh = pbox[b * 4 + 3];
    const int x1p = min(max((int)((cx - bw * 0.5f) * (float)W_), 0), W_);
    const int x2p = min(max((int)((cx + bw * 0.5f) * (float)W_), 0), W_);
    const int y1p = min(max((int)((cy - bh * 0.5f) * (float)H_), 0), H_);
    const int y2p = min(max((int)((cy + bh * 0.5f) * (float)H_), 0), H_);

    int xin = 0;
    #pragma unroll
    for (int j = 0; j < 4; ++j)
        if (x0 + j >= x1p && x0 + j < x2p) xin |= 1 << j;

    const int rowbase = c * 64;
    const float4* lg4 = (const float4*)(logits + (size_t)b * HW_) +
                        (((size_t)(rowbase + half)) << 7) + xq;
    const int4*   tg4 = (const int4*)  (tgt    + (size_t)b * HW_) +
                        (((size_t)(rowbase + half)) << 7) + xq;

    float sps = 0.f, sptq = 0.f, sbx = 0.f, sxt = 0.f, slg = 0.f;
    int st = 0, tneg = 0, area = 0, inter = 0, apos = 0;
    unsigned int rowm = 0;   // bit k set <=> any positive in row-pair k

    // ---- software-pipelined main loop: 16 steps of 2 row-pairs ----
    float4 xA[2], xB[2];
    int4   tA[2], tB[2];

    #define LOADP(BUF_X, BUF_T, S)                                 \
        do {                                                       \
            BUF_X[0] = lg4[(size_t)(2 * (S) + 0) * 256];           \
            BUF_X[1] = lg4[(size_t)(2 * (S) + 1) * 256];           \
            BUF_T[0] = tg4[(size_t)(2 * (S) + 0) * 256];           \
            BUF_T[1] = tg4[(size_t)(2 * (S) + 1) * 256];           \
        } while (0)

    #define PROCP(BUF_X, BUF_T, S)                                             \
        do {                                                                   \
            _Pragma("unroll")                                                  \
            for (int u = 0; u < 2; ++u) {                                      \
                const int k = 2 * (S) + u;                                     \
                const int y = rowbase + 2 * k + half;                          \
                const bool yin = (y >= y1p) && (y < y2p);                      \
                const float xs[4] = {BUF_X[u].x, BUF_X[u].y,                   \
                                     BUF_X[u].z, BUF_X[u].w};                  \
                const int   ti[4] = {BUF_T[u].x, BUF_T[u].y,                   \
                                     BUF_T[u].z, BUF_T[u].w};                  \
                int pb = 0;                                                    \
                _Pragma("unroll")                                              \
                for (int j = 0; j < 4; ++j) {                                  \
                    const float x = xs[j];                                     \
                    const float th = tanh_approx(0.5f * fabsf(x));             \
                    const float p0 = fmaf(0.5f, th, 0.5f);     /* sig(|x|) */  \
                    slg += __log2f(p0);                                        \
                    const float q  = copysignf(p0, x);         /* LOP3 */      \
                    const float tf = __int_as_float(ti[j] * 0x3f800000);       \
                    sps  += q;                                                 \
                    sptq  = fmaf(q, tf, sptq);                                 \
                    sxt   = fmaf(x, tf, sxt);                                  \
                    sbx  += fmaxf(x, 0.0f);                                    \
                    pb   |= (x > 0.0f) ? (1 << j) : 0;                         \
                }                                                              \
                const int tb = ti[0] + 2 * ti[1] + 4 * ti[2] + 8 * ti[3];      \
                st   += __popc(tb);                                            \
                tneg += __popc(tb & ~pb);                                      \
                area += __popc(pb);                                            \
                apos |= pb;                                                    \
                rowm |= pb ? (1u << k) : 0u;                                   \
                inter += yin ? __popc(pb & xin) : 0;                           \
            }                                                                  \
        } while (0)

    LOADP(xA, tA, 0);                     // prologue
    #pragma unroll 2
    for (int m = 0; m < 7; ++m) {
        LOADP(xB, tB, 2 * m + 1);         // prefetch next while A in regs
        PROCP(xA, tA, 2 * m);
        LOADP(xA, tA, 2 * m + 2);         // prefetch next-next
        PROCP(xB, tB, 2 * m + 1);
    }
    LOADP(xB, tB, 15);                    // epilogue
    PROCP(xA, tA, 14);
    PROCP(xB, tB, 15);

    #undef LOADP
    #undef PROCP

    // sum_p: p = q + (x<0 ? 1 : 0); #neg = 128 - area  (x != 0 a.s.)
    const float sp   = 128.0f - (float)area + sps;
    // sum_pt: p·t summed = sptq + #(t=1 & x<=0)
    const float spt  = (float)tneg + sptq;
    // bce = sum max(x,0) - sum x*t + ln2 * sum -log2(p0)
    const float sbce = sbx - sxt - 0.69314718055994531f * slg;

    const int mnx = apos ? (x0 + (__ffs(apos) - 1)) : W_;
    const int mxx = apos ? (x0 + (31 - __clz(apos))) : -1;
    const int ylo = rowm ? (rowbase + 2 * (__ffs((int)rowm) - 1) + half) : H_;
    const int yhi = rowm ? (rowbase + 2 * (31 - __clz((int)rowm)) + half) : -1;

    // Block reduce (warp shuffle + shared)
    __shared__ float shf[3][TPB / 32];
    __shared__ int   shi[7][TPB / 32];
    const int lane = tid & 31, wid = tid >> 5;

    float rsp  = warp_sum_f(sp);
    float rspt = warp_sum_f(spt);
    float rbce = warp_sum_f(sbce);
    int rst    = warp_sum_i(st);
    int rarea  = warp_sum_i(area);
    int rinter = warp_sum_i(inter);
    int rmnx   = warp_min_i(mnx);
    int rylo   = warp_min_i(ylo);
    int rmxx   = warp_max_i(mxx);
    int ryhi   = warp_max_i(yhi);

    if (lane == 0) {
        shf[0][wid] = rsp;  shf[1][wid] = rspt; shf[2][wid] = rbce;
        shi[0][wid] = rst;  shi[1][wid] = rarea; shi[2][wid] = rinter;
        shi[3][wid] = rmnx; shi[4][wid] = rylo;  shi[5][wid] = rmxx; shi[6][wid] = ryhi;
    }
    __syncthreads();

    __shared__ bool s_is_last;
    if (tid == 0) {
        float a0 = shf[0][0], a1 = shf[1][0], a2 = shf[2][0];
        int i0 = shi[0][0], i1 = shi[1][0], i2 = shi[2][0];
        int i3 = shi[3][0], i4 = shi[4][0], i5 = shi[5][0], i6 = shi[6][0];
        #pragma unroll
        for (int w = 1; w < TPB / 32; ++w) {
            a0 += shf[0][w]; a1 += shf[1][w]; a2 += shf[2][w];
            i0 += shi[0][w]; i1 += shi[1][w]; i2 += shi[2][w];
            i3 = min(i3, shi[3][w]); i4 = min(i4, shi[4][w]);
            i5 = max(i5, shi[5][w]); i6 = max(i6, shi[6][w]);
        }
        const int slot = b * BPS + c;
        g_fp[0 * NSLOT + slot] = a0;
        g_fp[1 * NSLOT + slot] = a1;
        g_fp[2 * NSLOT + slot] = a2;
        g_ip[0 * NSLOT + slot] = i0;
        g_ip[1 * NSLOT + slot] = i1;
        g_ip[2 * NSLOT + slot] = i2;
        g_ip[3 * NSLOT + slot] = i3;
        g_ip[4 * NSLOT + slot] = i4;
        g_ip[5 * NSLOT + slot] = i5;
        g_ip[6 * NSLOT + slot] = i6;

        __threadfence();
        const unsigned int prev = atomicAdd(&g_cnt, 1u);
        s_is_last = (prev == (unsigned int)(NSLOT - 1));
    }
    __syncthreads();
    if (!s_is_last) return;
    __threadfence();   // acquire: see all partials

    // ================= FINALIZE (last block only) =================
    __shared__ float s_dice[B_], s_bce[B_], s_s2b[B_], s_b2s[B_], s_det[B_];

    if (tid < B_) {
        const int s = tid;
        float fsp = 0.f, fspt = 0.f, fsbce = 0.f;
        int fst = 0, farea = 0, finter = 0;
        int fmnx = W_, fmny = H_, fmxx = -1, fmxy = -1;
        #pragma unroll
        for (int cc = 0; cc < BPS; ++cc) {
            const int slot = s * BPS + cc;
            fsp   += g_fp[0 * NSLOT + slot];
            fspt  += g_fp[1 * NSLOT + slot];
            fsbce += g_fp[2 * NSLOT + slot];
            fst   += g_ip[0 * NSLOT + slot];
            farea += g_ip[1 * NSLOT + slot];
            finter+= g_ip[2 * NSLOT + slot];
            fmnx = min(fmnx, g_ip[3 * NSLOT + slot]);
            fmny = min(fmny, g_ip[4 * NSLOT + slot]);
            fmxx = max(fmxx, g_ip[5 * NSLOT + slot]);
            fmxy = max(fmxy, g_ip[6 * NSLOT + slot]);
        }

        const float dice = 1.0f - (2.0f * fspt + 1.0f) / (fsp + (float)fst + 1.0f);

        const float iou_s2b = (farea > 0) ? ((float)finter / fmaxf((float)farea, 1.0f)) : 0.0f;
        const float s2b = 1.0f - iou_s2b;

        float pbv[4] = {pbox[s*4+0], pbox[s*4+1], pbox[s*4+2], pbox[s*4+3]};
        float box_xyxy[4];
        xywh2xyxy(pbv, box_xyxy);
        float outer[4];
        if (farea > 0) {
            outer[0] = (float)fmnx; outer[1] = (float)fmny;
            outer[2] = (float)fmxx; outer[3] = (float)fmxy;
        } else {
            outer[0] = outer[1] = outer[2] = outer[3] = 0.0f;
        }
        outer[0] /= (float)W_; outer[1] /= (float)H_;
        outer[2] /= (float)W_; outer[3] /= (float)H_;
        float pred_w[4], tgt_w[4];
        xyxy2xywh(outer, pred_w);
        xyxy2xywh(box_xyxy, tgt_w);
        const float b2s = box_loss(pred_w, tgt_w);

        float g[4] = {gbox[s*4+0], gbox[s*4+1], gbox[s*4+2], gbox[s*4+3]};
        const float gx1 = g[0] * (0.45f * (float)W_);
        const float gy1 = g[1] * (0.45f * (float)H_);
        const float gx2 = gx1 + 1.0f + g[2] * (0.5f * (float)W_);
        const float gy2 = gy1 + 1.0f + g[3] * (0.5f * (float)H_);
        float gxyxy[4] = {gx1, gy1, gx2, gy2};
        float gtw[4];
        xyxy2xywh(gxyxy, gtw);
        gtw[0] /= (float)H_; gtw[1] /= (float)W_;
        gtw[2] /= (float)H_; gtw[3] /= (float)W_;
        const float det = box_loss(pbv, gtw);

        s_dice[s] = dice; s_bce[s] = fsbce; s_s2b[s] = s2b; s_b2s[s] = b2s; s_det[s] = det;
    }
    __syncthreads();

    if (tid == 0) {
        float td = 0.f, tb = 0.f, ts2 = 0.f, t2 = 0.f, te = 0.f;
        for (int i = 0; i < B_; ++i) {
            td += s_dice[i]; tb += s_bce[i]; ts2 += s_s2b[i];
            t2 += s_b2s[i];  te += s_det[i];
        }
        const float inv_b = 1.0f / (float)B_;
        out[0] = td * inv_b
               + tb / ((float)B_ * (float)HW_)
               + te * inv_b * 0.025f
               + ts2 * inv_b
               + t2 * inv_b;
        g_cnt = 0;   // reset for next graph replay
    }
}

extern "C" void kernel_launch(void* const* d_in, const int* in_sizes, int n_in,
                              void* d_out, int out_size) {
    const float* pred_mask = (const float*)d_in[0];   // (64,1,512,512)
    const float* pred_bbox = (const float*)d_in[1];   // (64,4)
    const float* gt_bbox   = (const float*)d_in[2];   // (64,4)
    const int*   tgt_mask  = (const int*)  d_in[3];   // (64,512,512)
    float* out = (float*)d_out;

    dim3 grid(BPS, B_);
    uh_fused_kernel<<<grid, TPB>>>(pred_mask, tgt_mask, pred_bbox, gt_bbox, out);
}

// round 11
// speedup vs baseline: 1.2636x; 1.0010x over previous
#include <cuda_runtime.h>
#include <cuda_bf16.h>

#define B_   64
#define H_   512
#define W_   512
#define HW_  (H_ * W_)          // 262144
#define BPS  8                  // tiles per sample (64 rows each) -> 512 blocks total
#define TPB  256
#define NSLOT (B_ * BPS)        // 512 partial slots (== total blocks)

// Per-block partial reductions (SoA). Every slot written each launch -> no init needed.
__device__ float g_fp[3 * NSLOT];   // [0]=sum_p [1]=sum_pt [2]=sum_bce
__device__ int   g_ip[7 * NSLOT];   // [0]=sum_t [1]=area [2]=inter [3]=minx [4]=miny [5]=maxx [6]=maxy
__device__ unsigned int g_cnt;      // block completion counter (zero-init, reset by last block)

__device__ __forceinline__ float tanh_approx(float x) {
    float r;
    asm("tanh.approx.f32 %0, %1;" : "=f"(r) : "f"(x));
    return r;
}

// Gather the sign bytes of 4 floats into one word: byte j = 0xFF if x_j < 0 else 0x00.
__device__ __forceinline__ unsigned sign_bytes(float a0, float a1, float a2, float a3) {
    unsigned s01, s23, r;
    asm("prmt.b32 %0, %1, %2, 0x000000FB;" : "=r"(s01)
        : "r"(__float_as_uint(a0)), "r"(__float_as_uint(a1)));
    asm("prmt.b32 %0, %1, %2, 0x000000FB;" : "=r"(s23)
        : "r"(__float_as_uint(a2)), "r"(__float_as_uint(a3)));
    asm("prmt.b32 %0, %1, %2, 0x00005410;" : "=r"(r) : "r"(s01), "r"(s23));
    return r;
}

__device__ __forceinline__ float warp_sum_f(float v) {
    #pragma unroll
    for (int o = 16; o > 0; o >>= 1) v += __shfl_down_sync(0xffffffffu, v, o);
    return v;
}
__device__ __forceinline__ int warp_sum_i(int v) {
    #pragma unroll
    for (int o = 16; o > 0; o >>= 1) v += __shfl_down_sync(0xffffffffu, v, o);
    return v;
}
__device__ __forceinline__ int warp_min_i(int v) {
    #pragma unroll
    for (int o = 16; o > 0; o >>= 1) v = min(v, __shfl_down_sync(0xffffffffu, v, o));
    return v;
}
__device__ __forceinline__ int warp_max_i(int v) {
    #pragma unroll
    for (int o = 16; o > 0; o >>= 1) v = max(v, __shfl_down_sync(0xffffffffu, v, o));
    return v;
}

// ---------- scalar box helpers ----------
__device__ __forceinline__ void xywh2xyxy(const float* w, float* x) {
    x[0] = w[0] - w[2] * 0.5f; x[1] = w[1] - w[3] * 0.5f;
    x[2] = w[0] + w[2] * 0.5f; x[3] = w[1] + w[3] * 0.5f;
}
__device__ __forceinline__ void xyxy2xywh(const float* x, float* w) {
    w[0] = (x[0] + x[2]) * 0.5f; w[1] = (x[1] + x[3]) * 0.5f;
    w[2] = x[2] - x[0];          w[3] = x[3] - x[1];
}
__device__ __forceinline__ float giou_xyxy(const float* a, const float* b) {
    const float ix1 = fmaxf(a[0], b[0]), iy1 = fmaxf(a[1], b[1]);
    const float ix2 = fminf(a[2], b[2]), iy2 = fminf(a[3], b[3]);
    const float inter = fmaxf(ix2 - ix1, 0.f) * fmaxf(iy2 - iy1, 0.f);
    const float aa = fmaxf(a[2] - a[0], 0.f) * fmaxf(a[3] - a[1], 0.f);
    const float ab = fmaxf(b[2] - b[0], 0.f) * fmaxf(b[3] - b[1], 0.f);
    const float un = aa + ab - inter;
    const float iou = inter / fmaxf(un, 1e-6f);
    const float cx1 = fminf(a[0], b[0]), cy1 = fminf(a[1], b[1]);
    const float cx2 = fmaxf(a[2], b[2]), cy2 = fmaxf(a[3], b[3]);
    const float cc = fmaxf(cx2 - cx1, 0.f) * fmaxf(cy2 - cy1, 0.f);
    return iou - (cc - un) / fmaxf(cc, 1e-6f);
}
__device__ __forceinline__ float box_loss(const float* pw, const float* tw) {
    const float l1 = fabsf(pw[0] - tw[0]) + fabsf(pw[1] - tw[1]) +
                     fabsf(pw[2] - tw[2]) + fabsf(pw[3] - tw[3]);
    float ax[4], bx[4];
    xywh2xyxy(pw, ax); xywh2xyxy(tw, bx);
    return l1 + (1.0f - giou_xyxy(ax, bx));
}

__global__ __launch_bounds__(TPB, 4) void uh_fused_kernel(
    const float* __restrict__ logits,   // (B,1,H,W)
    const int*   __restrict__ tgt,      // (B,H,W)
    const float* __restrict__ pbox,     // (B,4) xywh normalized
    const float* __restrict__ gbox,     // (B,4)
    float* __restrict__ out)
{
    const int b   = blockIdx.y;
    const int c   = blockIdx.x;
    const int tid = threadIdx.x;

    const int xq   = tid & 127;          // float4 column index [0,128)
    const int half = tid >> 7;           // 0/1
    const int x0   = xq << 2;            // pixel column base

    // Box in pixel coords
    const float cx = pbox[b * 4 + 0], cy = pbox[b * 4 + 1];
    const float bw = pbox[b * 4 + 2], bh = pbox[b * 4 + 3];
    const int x1p = min(max((int)((cx - bw * 0.5f) * (float)W_), 0), W_);
    const int x2p = min(max((int)((cx + bw * 0.5f) * (float)W_), 0), W_);
    const int y1p = min(max((int)((cy - bh * 0.5f) * (float)H_), 0), H_);
    const int y2p = min(max((int)((cy + bh * 0.5f) * (float)H_), 0), H_);

    // Byte mask of my 4 columns inside [x1p, x2p): byte j = 0x01
    unsigned xinb = 0;
    #pragma unroll
    for (int j = 0; j < 4; ++j)
        if (x0 + j >= x1p && x0 + j < x2p) xinb |= 1u << (8 * j);

    const int rowbase = c * 64;
    const float4* lg4 = (const float4*)(logits + (size_t)b * HW_) +
                        (((size_t)(rowbase + half)) << 7) + xq;
    const int4*   tg4 = (const int4*)  (tgt    + (size_t)b * HW_) +
                        (((size_t)(rowbase + half)) << 7) + xq;

    float sps = 0.f, sptq = 0.f, sx = 0.f, sax = 0.f, sxt = 0.f, slg = 0.f;
    int st = 0, tneg = 0, area = 0, inter = 0;
    unsigned aposb = 0;      // byte-accumulated positive-column mask
    unsigned rowm = 0;       // bit k set <=> any positive in row-pair k

    // ---- software-pipelined main loop: 16 steps of 2 row-pairs ----
    float4 xA[2], xB[2];
    int4   tA[2], tB[2];

    #define LOADP(BUF_X, BUF_T, S)                                 \
        do {                                                       \
            BUF_X[0] = lg4[(size_t)(2 * (S) + 0) * 256];           \
            BUF_X[1] = lg4[(size_t)(2 * (S) + 1) * 256];           \
            BUF_T[0] = tg4[(size_t)(2 * (S) + 0) * 256];           \
            BUF_T[1] = tg4[(size_t)(2 * (S) + 1) * 256];           \
        } while (0)

    #define PROCP(BUF_X, BUF_T, S)                                             \
        do {                                                                   \
            _Pragma("unroll")                                                  \
            for (int u = 0; u < 2; ++u) {                                      \
                const int k = 2 * (S) + u;                                     \
                const int y = rowbase + 2 * k + half;                          \
                const bool yin = (y >= y1p) && (y < y2p);                      \
                const float xs[4] = {BUF_X[u].x, BUF_X[u].y,                   \
                                     BUF_X[u].z, BUF_X[u].w};                  \
                const int   ti[4] = {BUF_T[u].x, BUF_T[u].y,                   \
                                     BUF_T[u].z, BUF_T[u].w};                  \
                _Pragma("unroll")                                              \
                for (int j = 0; j < 4; ++j) {                                  \
                    const float x = xs[j];                                     \
                    const float th = tanh_approx(0.5f * fabsf(x));             \
                    const float p0 = fmaf(0.5f, th, 0.5f);     /* sig(|x|) */  \
                    slg += __log2f(p0);                                        \
                    const float q  = copysignf(p0, x);         /* LOP3 */      \
                    const float tf = __int_as_float(ti[j] * 0x3f800000);       \
                    sps  += q;                                                 \
                    sptq  = fmaf(q, tf, sptq);                                 \
                    sxt   = fmaf(x, tf, sxt);                                  \
                    sx   += x;                                                 \
                    sax  += fabsf(x);                                          \
                }                                                              \
                const unsigned posb =                                          \
                    ~sign_bytes(xs[0], xs[1], xs[2], xs[3]) & 0x01010101u;     \
                const unsigned tbb = (unsigned)(ti[0] + ti[1] * 256 +          \
                                     ti[2] * 65536 + ti[3] * 16777216);        \
                st    += __popc(tbb);                                          \
                tneg  += __popc(tbb & ~posb);                                  \
                area  += __popc(posb);                                         \
                aposb |= posb;                                                 \
                rowm  |= posb ? (1u << k) : 0u;                                \
                inter += yin ? __popc(posb & xinb) : 0;                        \
            }                                                                  \
        } while (0)

    LOADP(xA, tA, 0);                     // prologue
    #pragma unroll 2
    for (int m = 0; m < 7; ++m) {
        LOADP(xB, tB, 2 * m + 1);         // prefetch next while A in regs
        PROCP(xA, tA, 2 * m);
        LOADP(xA, tA, 2 * m + 2);         // prefetch next-next
        PROCP(xB, tB, 2 * m + 1);
    }
    LOADP(xB, tB, 15);                    // epilogue
    PROCP(xA, tA, 14);
    PROCP(xB, tB, 15);

    #undef LOADP
    #undef PROCP

    // sum_p: p = q + (x<0 ? 1 : 0); #neg = 128 - area  (x != 0 a.s.)
    const float sp   = 128.0f - (float)area + sps;
    // sum_pt: p·t summed = sptq + #(t=1 & x<0)
    const float spt  = (float)tneg + sptq;
    // bce = sum max(x,0) - sum x*t + ln2 * sum -log2(p0);  max(x,0) = (x+|x|)/2
    const float sbce = 0.5f * (sx + sax) - sxt - 0.69314718055994531f * slg;

    // Resolve per-thread extremes from byte/bit masks
    const int mnx = aposb ? (x0 + ((__ffs(aposb) - 1) >> 3)) : W_;
    const int mxx = aposb ? (x0 + ((31 - __clz(aposb)) >> 3)) : -1;
    const int ylo = rowm ? (rowbase + 2 * (__ffs((int)rowm) - 1) + half) : H_;
    const int yhi = rowm ? (rowbase + 2 * (31 - __clz((int)rowm)) + half) : -1;

    // Block reduce (warp shuffle + shared)
    __shared__ float shf[3][TPB / 32];
    __shared__ int   shi[7][TPB / 32];
    const int lane = tid & 31, wid = tid >> 5;

    float rsp  = warp_sum_f(sp);
    float rspt = warp_sum_f(spt);
    float rbce = warp_sum_f(sbce);
    int rst    = warp_sum_i(st);
    int rarea  = warp_sum_i(area);
    int rinter = warp_sum_i(inter);
    int rmnx   = warp_min_i(mnx);
    int rylo   = warp_min_i(ylo);
    int rmxx   = warp_max_i(mxx);
    int ryhi   = warp_max_i(yhi);

    if (lane == 0) {
        shf[0][wid] = rsp;  shf[1][wid] = rspt; shf[2][wid] = rbce;
        shi[0][wid] = rst;  shi[1][wid] = rarea; shi[2][wid] = rinter;
        shi[3][wid] = rmnx; shi[4][wid] = rylo;  shi[5][wid] = rmxx; shi[6][wid] = ryhi;
    }
    __syncthreads();

    __shared__ bool s_is_last;
    if (tid == 0) {
        float a0 = shf[0][0], a1 = shf[1][0], a2 = shf[2][0];
        int i0 = shi[0][0], i1 = shi[1][0], i2 = shi[2][0];
        int i3 = shi[3][0], i4 = shi[4][0], i5 = shi[5][0], i6 = shi[6][0];
        #pragma unroll
        for (int w = 1; w < TPB / 32; ++w) {
            a0 += shf[0][w]; a1 += shf[1][w]; a2 += shf[2][w];
            i0 += shi[0][w]; i1 += shi[1][w]; i2 += shi[2][w];
            i3 = min(i3, shi[3][w]); i4 = min(i4, shi[4][w]);
            i5 = max(i5, shi[5][w]); i6 = max(i6, shi[6][w]);
        }
        const int slot = b * BPS + c;
        g_fp[0 * NSLOT + slot] = a0;
        g_fp[1 * NSLOT + slot] = a1;
        g_fp[2 * NSLOT + slot] = a2;
        g_ip[0 * NSLOT + slot] = i0;
        g_ip[1 * NSLOT + slot] = i1;
        g_ip[2 * NSLOT + slot] = i2;
        g_ip[3 * NSLOT + slot] = i3;
        g_ip[4 * NSLOT + slot] = i4;
        g_ip[5 * NSLOT + slot] = i5;
        g_ip[6 * NSLOT + slot] = i6;

        __threadfence();
        const unsigned int prev = atomicAdd(&g_cnt, 1u);
        s_is_last = (prev == (unsigned int)(NSLOT - 1));
    }
    __syncthreads();
    if (!s_is_last) return;
    __threadfence();   // acquire: see all partials

    // ================= FINALIZE (last block only) =================
    __shared__ float s_dice[B_], s_bce[B_], s_s2b[B_], s_b2s[B_], s_det[B_];

    if (tid < B_) {
        const int s = tid;
        float fsp = 0.f, fspt = 0.f, fsbce = 0.f;
        int fst = 0, farea = 0, finter = 0;
        int fmnx = W_, fmny = H_, fmxx = -1, fmxy = -1;
        #pragma unroll
        for (int cc = 0; cc < BPS; ++cc) {
            const int slot = s * BPS + cc;
            fsp   += g_fp[0 * NSLOT + slot];
            fspt  += g_fp[1 * NSLOT + slot];
            fsbce += g_fp[2 * NSLOT + slot];
            fst   += g_ip[0 * NSLOT + slot];
            farea += g_ip[1 * NSLOT + slot];
            finter+= g_ip[2 * NSLOT + slot];
            fmnx = min(fmnx, g_ip[3 * NSLOT + slot]);
            fmny = min(fmny, g_ip[4 * NSLOT + slot]);
            fmxx = max(fmxx, g_ip[5 * NSLOT + slot]);
            fmxy = max(fmxy, g_ip[6 * NSLOT + slot]);
        }

        const float dice = 1.0f - (2.0f * fspt + 1.0f) / (fsp + (float)fst + 1.0f);

        const float iou_s2b = (farea > 0) ? ((float)finter / fmaxf((float)farea, 1.0f)) : 0.0f;
        const float s2b = 1.0f - iou_s2b;

        float pbv[4] = {pbox[s*4+0], pbox[s*4+1], pbox[s*4+2], pbox[s*4+3]};
        float box_xyxy[4];
        xywh2xyxy(pbv, box_xyxy);
        float outer[4];
        if (farea > 0) {
            outer[0] = (float)fmnx; outer[1] = (float)fmny;
            outer[2] = (float)fmxx; outer[3] = (float)fmxy;
        } else {
            outer[0] = outer[1] = outer[2] = outer[3] = 0.0f;
        }
        outer[0] /= (float)W_; outer[1] /= (float)H_;
        outer[2] /= (float)W_; outer[3] /= (float)H_;
        float pred_w[4], tgt_w[4];
        xyxy2xywh(outer, pred_w);
        xyxy2xywh(box_xyxy, tgt_w);
        const float b2s = box_loss(pred_w, tgt_w);

        float g[4] = {gbox[s*4+0], gbox[s*4+1], gbox[s*4+2], gbox[s*4+3]};
        const float gx1 = g[0] * (0.45f * (float)W_);
        const float gy1 = g[1] * (0.45f * (float)H_);
        const float gx2 = gx1 + 1.0f + g[2] * (0.5f * (float)W_);
        const float gy2 = gy1 + 1.0f + g[3] * (0.5f * (float)H_);
        float gxyxy[4] = {gx1, gy1, gx2, gy2};
        float gtw[4];
        xyxy2xywh(gxyxy, gtw);
        gtw[0] /= (float)H_; gtw[1] /= (float)W_;
        gtw[2] /= (float)H_; gtw[3] /= (float)W_;
        const float det = box_loss(pbv, gtw);

        s_dice[s] = dice; s_bce[s] = fsbce; s_s2b[s] = s2b; s_b2s[s] = b2s; s_det[s] = det;
    }
    __syncthreads();

    if (tid == 0) {
        float td = 0.f, tb = 0.f, ts2 = 0.f, t2 = 0.f, te = 0.f;
        for (int i = 0; i < B_; ++i) {
            td += s_dice[i]; tb += s_bce[i]; ts2 += s_s2b[i];
            t2 += s_b2s[i];  te += s_det[i];
        }
        const float inv_b = 1.0f / (float)B_;
        out[0] = td * inv_b
               + tb / ((float)B_ * (float)HW_)
               + te * inv_b * 0.025f
               + ts2 * inv_b
               + t2 * inv_b;
        g_cnt = 0;   // reset for next graph replay
    }
}

extern "C" void kernel_launch(void* const* d_in, const int* in_sizes, int n_in,
                              void* d_out, int out_size) {
    const float* pred_mask = (const float*)d_in[0];   // (64,1,512,512)
    const float* pred_bbox = (const float*)d_in[1];   // (64,4)
    const float* gt_bbox   = (const float*)d_in[2];   // (64,4)
    const int*   tgt_mask  = (const int*)  d_in[3];   // (64,512,512)
    float* out = (float*)d_out;

    dim3 grid(BPS, B_);
    uh_fused_kernel<<<grid, TPB>>>(pred_mask, tgt_mask, pred_bbox, gt_bbox, out);
}